// round 10
// baseline (speedup 1.0000x reference)
#include <cuda_runtime.h>
#include <cuda_fp16.h>
#include <mma.h>
#include <cstdint>

using namespace nvcuda;

#define NN   50000
#define PADN 50176
#define PADDEG 53248
#define NBLK 208                 // PADDEG / 256
#define EE   800000
#define HH   128
#define GG   64
#define OUTD 10

// ---------------- scratch (device globals; no dynamic allocation) ----------
__device__ __half g_h16a[(size_t)PADN * HH];  // gemm input / gather output
__device__ __half g_h16b[(size_t)PADN * HH];  // gemm output / gather input
__device__ __half g_w16[3 * HH * HH];         // fp16 weights
__device__ int    g_batch[NN];
__device__ int    g_deg[PADDEG];              // padded, zeroed
__device__ int    g_rowstart[NN + 1];
__device__ int    g_cursor[NN];
__device__ float  g_dinv[NN];
__device__ int    g_csri[EE];                 // src index only
__device__ int    g_bsum[NBLK];
__device__ int    g_boff[NBLK];
__device__ float  g_pooled[GG * HH];
__device__ float  g_cnts[GG];
__device__ int    g_is64;

__device__ __forceinline__ int clampN(int v) { return min(max(v, 0), NN - 1); }

// ---------------- setup -----------------------------------------------------
__global__ void k_zero() {
    int i = blockIdx.x * blockDim.x + threadIdx.x;
    if (i < PADDEG) g_deg[i] = 0;
    if (i < GG * HH) g_pooled[i] = 0.0f;
    if (i < GG) g_cnts[i] = 0.0f;
}

__global__ void k_cvtw(const float* __restrict__ W0,
                       const float* __restrict__ W1,
                       const float* __restrict__ W2) {
    const int WQ = HH * HH / 4;          // 4096
    int i = blockIdx.x * blockDim.x + threadIdx.x;
    if (i >= 3 * WQ) return;
    const float4* src;
    int off;
    if (i < WQ)          { src = (const float4*)W0; off = i; }
    else if (i < 2 * WQ) { src = (const float4*)W1; off = i - WQ; }
    else                 { src = (const float4*)W2; off = i - 2 * WQ; }
    float4 v = src[off];
    __half2 a = __floats2half2_rn(v.x, v.y);
    __half2 b = __floats2half2_rn(v.z, v.w);
    uint2 o;
    o.x = *(unsigned int*)&a;
    o.y = *(unsigned int*)&b;
    ((uint2*)g_w16)[i] = o;
}

__global__ void k_detect(const int* __restrict__ p) {
    __shared__ int any;
    if (threadIdx.x == 0) any = 0;
    __syncthreads();
    int v = 0;
    for (int i = threadIdx.x; i < 4096; i += blockDim.x) v |= p[2 * i + 1];
    if (v) atomicOr(&any, 1);
    __syncthreads();
    if (threadIdx.x == 0) g_is64 = any ? 0 : 1;
}

// degree histogram: 4 edges per thread, dst-only reads (int4 on int32 path)
__global__ void k_hist(const void* __restrict__ p) {
    int e4 = blockIdx.x * blockDim.x + threadIdx.x;
    if (e4 * 4 >= EE) return;
    if (!g_is64) {
        const int4* q = (const int4*)((const int*)p + EE);
        int4 v = q[e4];
        atomicAdd(&g_deg[clampN(v.x)], 1);
        atomicAdd(&g_deg[clampN(v.y)], 1);
        atomicAdd(&g_deg[clampN(v.z)], 1);
        atomicAdd(&g_deg[clampN(v.w)], 1);
    } else {
        const long long* q = (const long long*)p;
#pragma unroll
        for (int j = 0; j < 4; j++) {
            int d = clampN((int)q[EE + e4 * 4 + j]);
            atomicAdd(&g_deg[d], 1);
        }
    }
}

// convert batch AND count nodes-per-graph, warp-aggregated
__global__ void k_cvt_batch(const void* __restrict__ p) {
    int n = blockIdx.x * blockDim.x + threadIdx.x;
    if (n >= NN) return;
    int b;
    if (g_is64) b = (int)((const long long*)p)[n];
    else        b = ((const int*)p)[n];
    b = min(max(b, 0), GG - 1);
    g_batch[n] = b;
    unsigned am = __activemask();
    unsigned mask = __match_any_sync(am, b);
    int leader = __ffs(mask) - 1;
    if ((threadIdx.x & 31) == leader)
        atomicAdd(&g_cnts[b], (float)__popc(mask));
}

// ---------------- parallel 3-phase scan --------------------------------------
__global__ void __launch_bounds__(256) k_scan1() {
    __shared__ int sh[256];
    int t = threadIdx.x;
    int i = blockIdx.x * 256 + t;
    sh[t] = g_deg[i];
    __syncthreads();
#pragma unroll
    for (int off = 128; off > 0; off >>= 1) {
        if (t < off) sh[t] += sh[t + off];
        __syncthreads();
    }
    if (t == 0) g_bsum[blockIdx.x] = sh[0];
}

__global__ void __launch_bounds__(256) k_scan2() {
    __shared__ int sh[256];
    int t = threadIdx.x;
    int v = (t < NBLK) ? g_bsum[t] : 0;
    sh[t] = v;
    __syncthreads();
#pragma unroll
    for (int off = 1; off < 256; off <<= 1) {
        int u = (t >= off) ? sh[t - off] : 0;
        __syncthreads();
        sh[t] += u;
        __syncthreads();
    }
    if (t < NBLK) g_boff[t] = sh[t] - v;     // exclusive
}

__global__ void __launch_bounds__(256) k_scan3() {
    __shared__ int ws[8];
    int t = threadIdx.x;
    int i = blockIdx.x * 256 + t;
    int lane = t & 31, w = t >> 5;
    int v = g_deg[i];
    int inc = v;
#pragma unroll
    for (int off = 1; off < 32; off <<= 1) {
        int u = __shfl_up_sync(0xffffffffu, inc, off);
        if (lane >= off) inc += u;
    }
    if (lane == 31) ws[w] = inc;
    __syncthreads();
    if (t == 0) {
        int run = 0;
#pragma unroll
        for (int k = 0; k < 8; k++) { int tmp = ws[k]; ws[k] = run; run += tmp; }
    }
    __syncthreads();
    int excl = inc - v + ws[w] + g_boff[blockIdx.x];
    if (i <= NN) g_rowstart[i] = excl;
    if (i < NN) {
        g_cursor[i] = excl;
        g_dinv[i] = rsqrtf((float)v + 1.0f);
    }
}

// CSR fill: 4 edges per thread, int4 loads on int32 path
__global__ void k_fill(const void* __restrict__ p) {
    int e4 = blockIdx.x * blockDim.x + threadIdx.x;
    if (e4 * 4 >= EE) return;
    if (!g_is64) {
        const int4* qs = (const int4*)p;
        const int4* qd = (const int4*)((const int*)p + EE);
        int4 sv = qs[e4];
        int4 dv = qd[e4];
        int pos;
        pos = atomicAdd(&g_cursor[clampN(dv.x)], 1); g_csri[pos] = clampN(sv.x);
        pos = atomicAdd(&g_cursor[clampN(dv.y)], 1); g_csri[pos] = clampN(sv.y);
        pos = atomicAdd(&g_cursor[clampN(dv.z)], 1); g_csri[pos] = clampN(sv.z);
        pos = atomicAdd(&g_cursor[clampN(dv.w)], 1); g_csri[pos] = clampN(sv.w);
    } else {
        const long long* q = (const long long*)p;
#pragma unroll
        for (int j = 0; j < 4; j++) {
            int e = e4 * 4 + j;
            int s = clampN((int)q[e]);
            int d = clampN((int)q[EE + e]);
            int pos = atomicAdd(&g_cursor[d], 1);
            g_csri[pos] = s;
        }
    }
}

// ---------------- tensor-core GEMM -------------------------------------------
#define LDA 136
#define SMEM_GEMM (2 * 128 * LDA * (int)sizeof(__half))   // 69,632 B

template <typename LOADA>
__device__ __forceinline__ void gemm_body(LOADA loadA,
                                          const __half* __restrict__ W,
                                          __half* __restrict__ C,
                                          int nRows) {
    extern __shared__ __half sm[];
    __half* As = sm;                   // 128 x LDA
    __half* Ws = sm + 128 * LDA;       // 128 x LDA

    int tid  = threadIdx.x;
    int w    = tid >> 5;
    int row0 = blockIdx.x * 128;

    loadA(As, row0, tid, nRows);
#pragma unroll
    for (int i = 0; i < 8; i++) {
        int idx = tid + i * 256;
        int r  = idx >> 4;
        int c8 = idx & 15;
        uint4 v = *(const uint4*)(W + r * 128 + c8 * 8);
        *(uint4*)(Ws + r * LDA + c8 * 8) = v;
    }
    __syncthreads();

    int wr = w >> 1, wc = w & 1;
    int r0w = wr * 32, c0w = wc * 64;

    wmma::fragment<wmma::accumulator, 16, 16, 16, float> c[2][4];
#pragma unroll
    for (int i = 0; i < 2; i++)
#pragma unroll
        for (int j = 0; j < 4; j++) wmma::fill_fragment(c[i][j], 0.0f);

#pragma unroll
    for (int k0 = 0; k0 < 128; k0 += 16) {
        wmma::fragment<wmma::matrix_a, 16, 16, 16, __half, wmma::row_major> a[2];
        wmma::fragment<wmma::matrix_b, 16, 16, 16, __half, wmma::row_major> b[4];
#pragma unroll
        for (int i = 0; i < 2; i++)
            wmma::load_matrix_sync(a[i], As + (r0w + i * 16) * LDA + k0, LDA);
#pragma unroll
        for (int j = 0; j < 4; j++)
            wmma::load_matrix_sync(b[j], Ws + k0 * LDA + c0w + j * 16, LDA);
#pragma unroll
        for (int i = 0; i < 2; i++)
#pragma unroll
            for (int j = 0; j < 4; j++)
                wmma::mma_sync(c[i][j], a[i], b[j], c[i][j]);
    }

#pragma unroll
    for (int i = 0; i < 2; i++) {
#pragma unroll
        for (int j = 0; j < 4; j++) {
            wmma::fragment<wmma::accumulator, 16, 16, 16, __half> hc;
#pragma unroll
            for (int e = 0; e < hc.num_elements; e++)
                hc.x[e] = __float2half(c[i][j].x[e]);
            wmma::store_matrix_sync(C + (size_t)(row0 + r0w + i * 16) * 128 + c0w + j * 16,
                                    hc, 128, wmma::mem_row_major);
        }
    }
}

__global__ void __launch_bounds__(256) k_gemm(const __half* __restrict__ A,
                                              const __half* __restrict__ W,
                                              __half* __restrict__ C,
                                              int nRows) {
    gemm_body([A](__half* As, int row0, int tid, int nR) {
#pragma unroll
        for (int i = 0; i < 8; i++) {
            int idx = tid + i * 256;
            int r  = idx >> 4;
            int c8 = idx & 15;
            uint4 v = make_uint4(0u, 0u, 0u, 0u);
            if (row0 + r < nR)
                v = *(const uint4*)(A + (size_t)(row0 + r) * 128 + c8 * 8);
            *(uint4*)(As + r * LDA + c8 * 8) = v;
        }
    }, W, C, nRows);
}

__global__ void __launch_bounds__(256) k_gemm_f32in(const float* __restrict__ A,
                                                    const __half* __restrict__ W,
                                                    __half* __restrict__ C,
                                                    int nRows) {
    gemm_body([A](__half* As, int row0, int tid, int nR) {
#pragma unroll
        for (int i = 0; i < 16; i++) {
            int idx = tid + i * 256;
            int r  = idx >> 5;
            int c4 = idx & 31;
            float4 v = make_float4(0.f, 0.f, 0.f, 0.f);
            if (row0 + r < nR)
                v = *(const float4*)(A + (size_t)(row0 + r) * 128 + c4 * 4);
            __half2 a = __floats2half2_rn(v.x, v.y);
            __half2 b = __floats2half2_rn(v.z, v.w);
            uint2 o;
            o.x = *(unsigned int*)&a;
            o.y = *(unsigned int*)&b;
            *(uint2*)(As + r * LDA + c4 * 4) = o;
        }
    }, W, C, nRows);
}

// ---------------- CSR gather: full warp per node, lane-split halves ---------
// out[n] = dinv[n] * ( sum_s dinv[s]*h[s] + dinv[n]*h[n] )
__device__ __forceinline__ void unp8(uint4 v, float* f) {
    float2 a = __half22float2(*(__half2*)&v.x);
    float2 b = __half22float2(*(__half2*)&v.y);
    float2 c = __half22float2(*(__half2*)&v.z);
    float2 d = __half22float2(*(__half2*)&v.w);
    f[0] = a.x; f[1] = a.y; f[2] = b.x; f[3] = b.y;
    f[4] = c.x; f[5] = c.y; f[6] = d.x; f[7] = d.y;
}

__global__ void __launch_bounds__(256) k_gather(const __half* __restrict__ h,
                                                __half* __restrict__ out,
                                                int doRelu) {
    int warp = (blockIdx.x * blockDim.x + threadIdx.x) >> 5;
    int lane = threadIdx.x & 31;
    if (warp >= NN) return;
    int n = warp;
    int half = lane >> 4;                 // 0: even edges, 1: odd edges
    int l16  = lane & 15;

    const uint4* h4 = (const uint4*)h;
    float di = g_dinv[n];
    float acc[8] = {0.f, 0.f, 0.f, 0.f, 0.f, 0.f, 0.f, 0.f};
    float f0[8], f1[8], f2[8], f3[8];

    if (half == 0) {                      // self term on half 0 only
        unp8(h4[(size_t)n * 16 + l16], acc);
#pragma unroll
        for (int k = 0; k < 8; k++) acc[k] *= di;
    }

    int i   = g_rowstart[n];
    int end = g_rowstart[n + 1];
    // main: 8 edges per warp-iteration (4 per half), uniform trip count
    for (; i + 7 < end; i += 8) {
        int s0 = g_csri[i + half];
        int s1 = g_csri[i + 2 + half];
        int s2 = g_csri[i + 4 + half];
        int s3 = g_csri[i + 6 + half];
        float w0 = __ldg(&g_dinv[s0]), w1 = __ldg(&g_dinv[s1]);
        float w2 = __ldg(&g_dinv[s2]), w3 = __ldg(&g_dinv[s3]);
        uint4 v0 = h4[(size_t)s0 * 16 + l16];
        uint4 v1 = h4[(size_t)s1 * 16 + l16];
        uint4 v2 = h4[(size_t)s2 * 16 + l16];
        uint4 v3 = h4[(size_t)s3 * 16 + l16];
        unp8(v0, f0); unp8(v1, f1); unp8(v2, f2); unp8(v3, f3);
#pragma unroll
        for (int k = 0; k < 8; k++)
            acc[k] += w0 * f0[k] + w1 * f1[k] + w2 * f2[k] + w3 * f3[k];
    }
    // pairs: 2 edges per warp-iteration
    for (; i + 1 < end; i += 2) {
        int s0 = g_csri[i + half];
        float w0 = __ldg(&g_dinv[s0]);
        uint4 v0 = h4[(size_t)s0 * 16 + l16];
        unp8(v0, f0);
#pragma unroll
        for (int k = 0; k < 8; k++) acc[k] += w0 * f0[k];
    }
    // odd leftover edge: half 0 only
    if (i < end && half == 0) {
        int s0 = g_csri[i];
        float w0 = __ldg(&g_dinv[s0]);
        uint4 v0 = h4[(size_t)s0 * 16 + l16];
        unp8(v0, f0);
#pragma unroll
        for (int k = 0; k < 8; k++) acc[k] += w0 * f0[k];
    }

    // combine halves (all 32 lanes participate)
#pragma unroll
    for (int k = 0; k < 8; k++)
        acc[k] += __shfl_xor_sync(0xffffffffu, acc[k], 16);

#pragma unroll
    for (int k = 0; k < 8; k++) acc[k] *= di;
    if (doRelu) {
#pragma unroll
        for (int k = 0; k < 8; k++) acc[k] = fmaxf(acc[k], 0.0f);
    }
    if (half == 0) {
        __half2 p0 = __floats2half2_rn(acc[0], acc[1]);
        __half2 p1 = __floats2half2_rn(acc[2], acc[3]);
        __half2 p2 = __floats2half2_rn(acc[4], acc[5]);
        __half2 p3 = __floats2half2_rn(acc[6], acc[7]);
        uint4 o;
        o.x = *(unsigned int*)&p0;
        o.y = *(unsigned int*)&p1;
        o.z = *(unsigned int*)&p2;
        o.w = *(unsigned int*)&p3;
        ((uint4*)out)[(size_t)n * 16 + l16] = o;
    }
}

// ---------------- pooling: warp per 64-node chunk, uint2 loads ---------------
__global__ void __launch_bounds__(128) k_pool(const __half* __restrict__ h) {
    int warp = threadIdx.x >> 5;
    int lane = threadIdx.x & 31;
    int n0 = blockIdx.x * 256 + warp * 64;
    if (n0 >= NN) return;
    int n1 = n0 + 64; if (n1 > NN) n1 = NN;

    const uint2* h2 = (const uint2*)h;
    float a0 = 0.f, a1 = 0.f, a2 = 0.f, a3 = 0.f;
    int g = g_batch[n0];
    for (int n = n0; n < n1; n++) {
        int b = g_batch[n];
        if (b != g) {
            int base = g * HH + lane * 4;
            atomicAdd(&g_pooled[base + 0], a0);
            atomicAdd(&g_pooled[base + 1], a1);
            atomicAdd(&g_pooled[base + 2], a2);
            atomicAdd(&g_pooled[base + 3], a3);
            a0 = a1 = a2 = a3 = 0.f;
            g = b;
        }
        uint2 v = h2[(size_t)n * 32 + lane];
        float2 x = __half22float2(*(__half2*)&v.x);
        float2 y = __half22float2(*(__half2*)&v.y);
        a0 += x.x; a1 += x.y; a2 += y.x; a3 += y.y;
    }
    int base = g * HH + lane * 4;
    atomicAdd(&g_pooled[base + 0], a0);
    atomicAdd(&g_pooled[base + 1], a1);
    atomicAdd(&g_pooled[base + 2], a2);
    atomicAdd(&g_pooled[base + 3], a3);
}

// ---------------- final MLP: one block per graph -----------------------------
__global__ void __launch_bounds__(128) k_mlp(const float* __restrict__ M0w,
                                             const float* __restrict__ M0b,
                                             const float* __restrict__ M1w,
                                             const float* __restrict__ M1b,
                                             float* __restrict__ out) {
    __shared__ float pv[HH];
    __shared__ float hid[HH];
    int g = blockIdx.x;
    int t = threadIdx.x;
    pv[t] = g_pooled[g * HH + t] / fmaxf(g_cnts[g], 1.0f);
    __syncthreads();
    float s = M0b[t];
#pragma unroll 8
    for (int k = 0; k < HH; k++) s += pv[k] * M0w[k * HH + t];
    hid[t] = fmaxf(s, 0.0f);
    __syncthreads();
    if (t < OUTD) {
        float s2 = M1b[t];
#pragma unroll 8
        for (int j = 0; j < HH; j++) s2 += hid[j] * M1w[j * OUTD + t];
        out[g * OUTD + t] = s2;
    }
}

// ---------------- launch ----------------------------------------------------
extern "C" void kernel_launch(void* const* d_in, const int* in_sizes, int n_in,
                              void* d_out, int out_size) {
    const float* x   = (const float*)d_in[0];
    const float* W0  = (const float*)d_in[1];
    const float* W1  = (const float*)d_in[2];
    const float* W2  = (const float*)d_in[3];
    const float* M0w = (const float*)d_in[4];
    const float* M0b = (const float*)d_in[5];
    const float* M1w = (const float*)d_in[6];
    const float* M1b = (const float*)d_in[7];
    const void*  ei  = d_in[8];
    const void*  bat = d_in[9];
    float* out = (float*)d_out;

    __half* hA = nullptr;
    __half* hB = nullptr;
    __half* w16 = nullptr;
    cudaGetSymbolAddress((void**)&hA, g_h16a);
    cudaGetSymbolAddress((void**)&hB, g_h16b);
    cudaGetSymbolAddress((void**)&w16, g_w16);

    static int attr_done = 0;
    if (!attr_done) {
        cudaFuncSetAttribute(k_gemm, cudaFuncAttributeMaxDynamicSharedMemorySize, SMEM_GEMM);
        cudaFuncSetAttribute(k_gemm_f32in, cudaFuncAttributeMaxDynamicSharedMemorySize, SMEM_GEMM);
        attr_done = 1;
    }

    const int T = 256;
    int gZ = (PADDEG + T - 1) / T;          // 208
    int gN = (NN + T - 1) / T;              // 196
    int gE4 = (EE / 4 + T - 1) / T;         // 782
    int gGemm    = (NN + 127) / 128;        // 391
    int gGatherW = (NN * 32 + T - 1) / T;   // 6250
    int gW       = (3 * HH * HH / 4 + T - 1) / T;  // 48

    // profiled launch is index 3 -> vectorized k_hist this round
    k_zero<<<gZ, T>>>();                                        // 0
    k_detect<<<1, 256>>>((const int*)ei);                       // 1
    k_cvtw<<<gW, T>>>(W0, W1, W2);                              // 2
    k_hist<<<gE4, T>>>(ei);                                     // 3  <- profiled
    k_scan1<<<NBLK, 256>>>();                                   // 4
    k_scan2<<<1, 256>>>();                                      // 5
    k_scan3<<<NBLK, 256>>>();                                   // 6
    k_fill<<<gE4, T>>>(ei);                                     // 7
    k_gemm_f32in<<<gGemm, T, SMEM_GEMM>>>(x, w16, hB, NN);      // 8
    k_cvt_batch<<<gN, T>>>(bat);                                // 9

    k_gather<<<gGatherW, T>>>(hB, hA, 1);                       // layer 1 agg
    k_gemm<<<gGemm, T, SMEM_GEMM>>>(hA, w16 + HH * HH, hB, NN);
    k_gather<<<gGatherW, T>>>(hB, hA, 1);                       // layer 2
    k_gemm<<<gGemm, T, SMEM_GEMM>>>(hA, w16 + 2 * HH * HH, hB, NN);
    k_gather<<<gGatherW, T>>>(hB, hA, 0);                       // layer 3

    k_pool<<<(NN + 255) / 256, 128>>>(hA);
    k_mlp<<<GG, 128>>>(M0w, M0b, M1w, M1b, out);
}

// round 11
// speedup vs baseline: 1.1022x; 1.1022x over previous
#include <cuda_runtime.h>
#include <cuda_fp16.h>
#include <mma.h>
#include <cstdint>

using namespace nvcuda;

#define NN   50000
#define PADN 50176
#define PADDEG 53248
#define NBLK 208                 // PADDEG / 256
#define EE   800000
#define HH   128
#define GG   64
#define OUTD 10

// ---------------- scratch (device globals; no dynamic allocation) ----------
__device__ __half g_h16a[(size_t)PADN * HH];  // gemm input / gather output
__device__ __half g_h16b[(size_t)PADN * HH];  // gemm output / gather input
__device__ __half g_w16[3 * HH * HH];         // fp16 weights
__device__ int    g_batch[NN];
__device__ int    g_deg[PADDEG];              // padded, zeroed
__device__ int    g_rowstart[NN + 1];
__device__ int    g_cursor[NN];
__device__ float  g_dinv[NN];
__device__ int    g_csri[EE];                 // src index only
__device__ int    g_bsum[NBLK];
__device__ float  g_pooled[GG * HH];
__device__ float  g_cnts[GG];
__device__ int    g_is64;

__device__ __forceinline__ int clampN(int v) { return min(max(v, 0), NN - 1); }

// ---------------- edge decode helper ----------------------------------------
__device__ __forceinline__ void decode_edge(const void* p, int e, int& s, int& d) {
    if (g_is64) {
        const long long* q = (const long long*)p;
        s = (int)q[e];
        d = (int)q[EE + e];
    } else {
        const int* q = (const int*)p;
        s = q[e];
        d = q[EE + e];
    }
    s = clampN(s);
    d = clampN(d);
}

// ---------------- init: zero scratch (blocks 0..207) + dtype detect (208) ---
__global__ void k_init(const int* __restrict__ p) {
    if (blockIdx.x < NBLK) {
        int i = blockIdx.x * 256 + threadIdx.x;
        g_deg[i] = 0;
        if (i < GG * HH) g_pooled[i] = 0.0f;
        if (i < GG) g_cnts[i] = 0.0f;
    } else {
        __shared__ int any;
        if (threadIdx.x == 0) any = 0;
        __syncthreads();
        int v = 0;
        for (int i = threadIdx.x; i < 4096; i += blockDim.x) v |= p[2 * i + 1];
        if (v) atomicOr(&any, 1);
        __syncthreads();
        if (threadIdx.x == 0) g_is64 = any ? 0 : 1;
    }
}

__global__ void k_cvtw(const float* __restrict__ W0,
                       const float* __restrict__ W1,
                       const float* __restrict__ W2) {
    const int WQ = HH * HH / 4;          // 4096
    int i = blockIdx.x * blockDim.x + threadIdx.x;
    if (i >= 3 * WQ) return;
    const float4* src;
    int off;
    if (i < WQ)          { src = (const float4*)W0; off = i; }
    else if (i < 2 * WQ) { src = (const float4*)W1; off = i - WQ; }
    else                 { src = (const float4*)W2; off = i - 2 * WQ; }
    float4 v = src[off];
    __half2 a = __floats2half2_rn(v.x, v.y);
    __half2 b = __floats2half2_rn(v.z, v.w);
    uint2 o;
    o.x = *(unsigned int*)&a;
    o.y = *(unsigned int*)&b;
    ((uint2*)g_w16)[i] = o;
}

// degree histogram (scalar per-edge: measured 10.7us; vectorized was neutral)
__global__ void k_hist(const void* __restrict__ p) {
    int e = blockIdx.x * blockDim.x + threadIdx.x;
    if (e >= EE) return;
    int s, d;
    decode_edge(p, e, s, d);
    atomicAdd(&g_deg[d], 1);
}

// convert batch AND count nodes-per-graph, warp-aggregated
__global__ void k_cvt_batch(const void* __restrict__ p) {
    int n = blockIdx.x * blockDim.x + threadIdx.x;
    if (n >= NN) return;
    int b;
    if (g_is64) b = (int)((const long long*)p)[n];
    else        b = ((const int*)p)[n];
    b = min(max(b, 0), GG - 1);
    g_batch[n] = b;
    unsigned am = __activemask();
    unsigned mask = __match_any_sync(am, b);
    int leader = __ffs(mask) - 1;
    if ((threadIdx.x & 31) == leader)
        atomicAdd(&g_cnts[b], (float)__popc(mask));
}

// ---------------- parallel scan (2 kernels) ----------------------------------
__global__ void __launch_bounds__(256) k_scan1() {
    __shared__ int sh[256];
    int t = threadIdx.x;
    int i = blockIdx.x * 256 + t;
    sh[t] = g_deg[i];
    __syncthreads();
#pragma unroll
    for (int off = 128; off > 0; off >>= 1) {
        if (t < off) sh[t] += sh[t + off];
        __syncthreads();
    }
    if (t == 0) g_bsum[blockIdx.x] = sh[0];
}

// scan3: redundant in-block scan of the 208 block sums + intra-block scan;
// emits rowstart / cursor / dinv.
__global__ void __launch_bounds__(256) k_scan3() {
    __shared__ int bs[256];
    __shared__ int ws[8];
    __shared__ int boff_s;
    int t = threadIdx.x;
    // exclusive prefix of block sums (redundant per block; 208 entries)
    bs[t] = (t < NBLK) ? g_bsum[t] : 0;
    __syncthreads();
#pragma unroll
    for (int off = 1; off < 256; off <<= 1) {
        int u = (t >= off) ? bs[t - off] : 0;
        __syncthreads();
        bs[t] += u;
        __syncthreads();
    }
    if (t == 0) boff_s = (blockIdx.x == 0) ? 0 : bs[blockIdx.x - 1];
    __syncthreads();

    int i = blockIdx.x * 256 + t;
    int lane = t & 31, w = t >> 5;
    int v = g_deg[i];
    int inc = v;
#pragma unroll
    for (int off = 1; off < 32; off <<= 1) {
        int u = __shfl_up_sync(0xffffffffu, inc, off);
        if (lane >= off) inc += u;
    }
    if (lane == 31) ws[w] = inc;
    __syncthreads();
    if (t == 0) {
        int run = 0;
#pragma unroll
        for (int k = 0; k < 8; k++) { int tmp = ws[k]; ws[k] = run; run += tmp; }
    }
    __syncthreads();
    int excl = inc - v + ws[w] + boff_s;
    if (i <= NN) g_rowstart[i] = excl;
    if (i < NN) {
        g_cursor[i] = excl;
        g_dinv[i] = rsqrtf((float)v + 1.0f);
    }
}

// CSR fill (scalar per-edge)
__global__ void k_fill(const void* __restrict__ p) {
    int e = blockIdx.x * blockDim.x + threadIdx.x;
    if (e >= EE) return;
    int s, d;
    decode_edge(p, e, s, d);
    int pos = atomicAdd(&g_cursor[d], 1);
    g_csri[pos] = s;
}

// ---------------- tensor-core GEMM -------------------------------------------
#define LDA 136
#define SMEM_GEMM (2 * 128 * LDA * (int)sizeof(__half))   // 69,632 B

template <typename LOADA>
__device__ __forceinline__ void gemm_body(LOADA loadA,
                                          const __half* __restrict__ W,
                                          __half* __restrict__ C,
                                          int nRows) {
    extern __shared__ __half sm[];
    __half* As = sm;                   // 128 x LDA
    __half* Ws = sm + 128 * LDA;       // 128 x LDA

    int tid  = threadIdx.x;
    int w    = tid >> 5;
    int row0 = blockIdx.x * 128;

    loadA(As, row0, tid, nRows);
#pragma unroll
    for (int i = 0; i < 8; i++) {
        int idx = tid + i * 256;
        int r  = idx >> 4;
        int c8 = idx & 15;
        uint4 v = *(const uint4*)(W + r * 128 + c8 * 8);
        *(uint4*)(Ws + r * LDA + c8 * 8) = v;
    }
    __syncthreads();

    int wr = w >> 1, wc = w & 1;
    int r0w = wr * 32, c0w = wc * 64;

    wmma::fragment<wmma::accumulator, 16, 16, 16, float> c[2][4];
#pragma unroll
    for (int i = 0; i < 2; i++)
#pragma unroll
        for (int j = 0; j < 4; j++) wmma::fill_fragment(c[i][j], 0.0f);

#pragma unroll
    for (int k0 = 0; k0 < 128; k0 += 16) {
        wmma::fragment<wmma::matrix_a, 16, 16, 16, __half, wmma::row_major> a[2];
        wmma::fragment<wmma::matrix_b, 16, 16, 16, __half, wmma::row_major> b[4];
#pragma unroll
        for (int i = 0; i < 2; i++)
            wmma::load_matrix_sync(a[i], As + (r0w + i * 16) * LDA + k0, LDA);
#pragma unroll
        for (int j = 0; j < 4; j++)
            wmma::load_matrix_sync(b[j], Ws + k0 * LDA + c0w + j * 16, LDA);
#pragma unroll
        for (int i = 0; i < 2; i++)
#pragma unroll
            for (int j = 0; j < 4; j++)
                wmma::mma_sync(c[i][j], a[i], b[j], c[i][j]);
    }

#pragma unroll
    for (int i = 0; i < 2; i++) {
#pragma unroll
        for (int j = 0; j < 4; j++) {
            wmma::fragment<wmma::accumulator, 16, 16, 16, __half> hc;
#pragma unroll
            for (int e = 0; e < hc.num_elements; e++)
                hc.x[e] = __float2half(c[i][j].x[e]);
            wmma::store_matrix_sync(C + (size_t)(row0 + r0w + i * 16) * 128 + c0w + j * 16,
                                    hc, 128, wmma::mem_row_major);
        }
    }
}

__global__ void __launch_bounds__(256) k_gemm(const __half* __restrict__ A,
                                              const __half* __restrict__ W,
                                              __half* __restrict__ C,
                                              int nRows) {
    gemm_body([A](__half* As, int row0, int tid, int nR) {
#pragma unroll
        for (int i = 0; i < 8; i++) {
            int idx = tid + i * 256;
            int r  = idx >> 4;
            int c8 = idx & 15;
            uint4 v = make_uint4(0u, 0u, 0u, 0u);
            if (row0 + r < nR)
                v = *(const uint4*)(A + (size_t)(row0 + r) * 128 + c8 * 8);
            *(uint4*)(As + r * LDA + c8 * 8) = v;
        }
    }, W, C, nRows);
}

__global__ void __launch_bounds__(256) k_gemm_f32in(const float* __restrict__ A,
                                                    const __half* __restrict__ W,
                                                    __half* __restrict__ C,
                                                    int nRows) {
    gemm_body([A](__half* As, int row0, int tid, int nR) {
#pragma unroll
        for (int i = 0; i < 16; i++) {
            int idx = tid + i * 256;
            int r  = idx >> 5;
            int c4 = idx & 31;
            float4 v = make_float4(0.f, 0.f, 0.f, 0.f);
            if (row0 + r < nR)
                v = *(const float4*)(A + (size_t)(row0 + r) * 128 + c4 * 4);
            __half2 a = __floats2half2_rn(v.x, v.y);
            __half2 b = __floats2half2_rn(v.z, v.w);
            uint2 o;
            o.x = *(unsigned int*)&a;
            o.y = *(unsigned int*)&b;
            *(uint2*)(As + r * LDA + c4 * 4) = o;
        }
    }, W, C, nRows);
}

// ---------------- CSR gather: half-warp per node (R9 best) ------------------
// out[n] = dinv[n] * ( sum_s dinv[s]*h[s] + dinv[n]*h[n] )
__device__ __forceinline__ void unp8(uint4 v, float* f) {
    float2 a = __half22float2(*(__half2*)&v.x);
    float2 b = __half22float2(*(__half2*)&v.y);
    float2 c = __half22float2(*(__half2*)&v.z);
    float2 d = __half22float2(*(__half2*)&v.w);
    f[0] = a.x; f[1] = a.y; f[2] = b.x; f[3] = b.y;
    f[4] = c.x; f[5] = c.y; f[6] = d.x; f[7] = d.y;
}

__global__ void __launch_bounds__(256) k_gather(const __half* __restrict__ h,
                                                __half* __restrict__ out,
                                                int doRelu) {
    int hw   = (blockIdx.x * blockDim.x + threadIdx.x) >> 4;
    int lane = threadIdx.x & 15;
    if (hw >= NN) return;
    int n = hw;

    const uint4* h4 = (const uint4*)h;
    float di = g_dinv[n];
    float acc[8], f0[8], f1[8], f2[8], f3[8];
    unp8(h4[(size_t)n * 16 + lane], acc);
#pragma unroll
    for (int k = 0; k < 8; k++) acc[k] *= di;   // self term: di*h[n]

    int i   = g_rowstart[n];
    int end = g_rowstart[n + 1];
    for (; i + 3 < end; i += 4) {
        int s0 = g_csri[i],     s1 = g_csri[i + 1];
        int s2 = g_csri[i + 2], s3 = g_csri[i + 3];
        float w0 = __ldg(&g_dinv[s0]), w1 = __ldg(&g_dinv[s1]);
        float w2 = __ldg(&g_dinv[s2]), w3 = __ldg(&g_dinv[s3]);
        uint4 v0 = h4[(size_t)s0 * 16 + lane];
        uint4 v1 = h4[(size_t)s1 * 16 + lane];
        uint4 v2 = h4[(size_t)s2 * 16 + lane];
        uint4 v3 = h4[(size_t)s3 * 16 + lane];
        unp8(v0, f0); unp8(v1, f1); unp8(v2, f2); unp8(v3, f3);
#pragma unroll
        for (int k = 0; k < 8; k++)
            acc[k] += w0 * f0[k] + w1 * f1[k] + w2 * f2[k] + w3 * f3[k];
    }
    for (; i < end; i++) {
        int s0 = g_csri[i];
        float w0 = __ldg(&g_dinv[s0]);
        uint4 v0 = h4[(size_t)s0 * 16 + lane];
        unp8(v0, f0);
#pragma unroll
        for (int k = 0; k < 8; k++) acc[k] += w0 * f0[k];
    }
#pragma unroll
    for (int k = 0; k < 8; k++) acc[k] *= di;
    if (doRelu) {
#pragma unroll
        for (int k = 0; k < 8; k++) acc[k] = fmaxf(acc[k], 0.0f);
    }
    __half2 p0 = __floats2half2_rn(acc[0], acc[1]);
    __half2 p1 = __floats2half2_rn(acc[2], acc[3]);
    __half2 p2 = __floats2half2_rn(acc[4], acc[5]);
    __half2 p3 = __floats2half2_rn(acc[6], acc[7]);
    uint4 o;
    o.x = *(unsigned int*)&p0;
    o.y = *(unsigned int*)&p1;
    o.z = *(unsigned int*)&p2;
    o.w = *(unsigned int*)&p3;
    ((uint4*)out)[(size_t)n * 16 + lane] = o;
}

// ---------------- pooling: warp per 64-node chunk, uint2 loads ---------------
__global__ void __launch_bounds__(128) k_pool(const __half* __restrict__ h) {
    int warp = threadIdx.x >> 5;
    int lane = threadIdx.x & 31;
    int n0 = blockIdx.x * 256 + warp * 64;
    if (n0 >= NN) return;
    int n1 = n0 + 64; if (n1 > NN) n1 = NN;

    const uint2* h2 = (const uint2*)h;
    float a0 = 0.f, a1 = 0.f, a2 = 0.f, a3 = 0.f;
    int g = g_batch[n0];
    for (int n = n0; n < n1; n++) {
        int b = g_batch[n];
        if (b != g) {
            int base = g * HH + lane * 4;
            atomicAdd(&g_pooled[base + 0], a0);
            atomicAdd(&g_pooled[base + 1], a1);
            atomicAdd(&g_pooled[base + 2], a2);
            atomicAdd(&g_pooled[base + 3], a3);
            a0 = a1 = a2 = a3 = 0.f;
            g = b;
        }
        uint2 v = h2[(size_t)n * 32 + lane];
        float2 x = __half22float2(*(__half2*)&v.x);
        float2 y = __half22float2(*(__half2*)&v.y);
        a0 += x.x; a1 += x.y; a2 += y.x; a3 += y.y;
    }
    int base = g * HH + lane * 4;
    atomicAdd(&g_pooled[base + 0], a0);
    atomicAdd(&g_pooled[base + 1], a1);
    atomicAdd(&g_pooled[base + 2], a2);
    atomicAdd(&g_pooled[base + 3], a3);
}

// ---------------- final MLP: one block per graph -----------------------------
__global__ void __launch_bounds__(128) k_mlp(const float* __restrict__ M0w,
                                             const float* __restrict__ M0b,
                                             const float* __restrict__ M1w,
                                             const float* __restrict__ M1b,
                                             float* __restrict__ out) {
    __shared__ float pv[HH];
    __shared__ float hid[HH];
    int g = blockIdx.x;
    int t = threadIdx.x;
    pv[t] = g_pooled[g * HH + t] / fmaxf(g_cnts[g], 1.0f);
    __syncthreads();
    float s = M0b[t];
#pragma unroll 8
    for (int k = 0; k < HH; k++) s += pv[k] * M0w[k * HH + t];
    hid[t] = fmaxf(s, 0.0f);
    __syncthreads();
    if (t < OUTD) {
        float s2 = M1b[t];
#pragma unroll 8
        for (int j = 0; j < HH; j++) s2 += hid[j] * M1w[j * OUTD + t];
        out[g * OUTD + t] = s2;
    }
}

// ---------------- launch ----------------------------------------------------
extern "C" void kernel_launch(void* const* d_in, const int* in_sizes, int n_in,
                              void* d_out, int out_size) {
    const float* x   = (const float*)d_in[0];
    const float* W0  = (const float*)d_in[1];
    const float* W1  = (const float*)d_in[2];
    const float* W2  = (const float*)d_in[3];
    const float* M0w = (const float*)d_in[4];
    const float* M0b = (const float*)d_in[5];
    const float* M1w = (const float*)d_in[6];
    const float* M1b = (const float*)d_in[7];
    const void*  ei  = d_in[8];
    const void*  bat = d_in[9];
    float* out = (float*)d_out;

    __half* hA = nullptr;
    __half* hB = nullptr;
    __half* w16 = nullptr;
    cudaGetSymbolAddress((void**)&hA, g_h16a);
    cudaGetSymbolAddress((void**)&hB, g_h16b);
    cudaGetSymbolAddress((void**)&w16, g_w16);

    static int init_done = 0;
    static cudaStream_t s2 = nullptr;
    static cudaEvent_t ev0 = nullptr, ev1 = nullptr;
    static int streams_ok = 0;
    if (!init_done) {
        cudaFuncSetAttribute(k_gemm, cudaFuncAttributeMaxDynamicSharedMemorySize, SMEM_GEMM);
        cudaFuncSetAttribute(k_gemm_f32in, cudaFuncAttributeMaxDynamicSharedMemorySize, SMEM_GEMM);
        if (cudaStreamCreateWithFlags(&s2, cudaStreamNonBlocking) == cudaSuccess &&
            cudaEventCreateWithFlags(&ev0, cudaEventDisableTiming) == cudaSuccess &&
            cudaEventCreateWithFlags(&ev1, cudaEventDisableTiming) == cudaSuccess)
            streams_ok = 1;
        init_done = 1;
    }

    const int T = 256;
    int gN = (NN + T - 1) / T;              // 196
    int gE = (EE + T - 1) / T;              // 3125
    int gGemm   = (NN + 127) / 128;         // 391
    int gGather = (NN * 16 + T - 1) / T;    // 3125
    int gW      = (3 * HH * HH / 4 + T - 1) / T;   // 48

    cudaStream_t sb = streams_ok ? s2 : (cudaStream_t)0;

    // init (zero + detect), then fork chains A (CSR) / B (weights+gemm1+batch)
    k_init<<<NBLK + 1, 256>>>((const int*)ei);                  // 0
    if (streams_ok) {
        cudaEventRecord(ev0, 0);
        cudaStreamWaitEvent(s2, ev0, 0);
    }
    // chain A on capture stream: CSR build
    k_hist<<<gE, T>>>(ei);                                      // 1
    k_scan1<<<NBLK, 256>>>();                                   // 2
    k_scan3<<<NBLK, 256>>>();                                   // 3  <- profiled
    k_fill<<<gE, T>>>(ei);                                      // 4
    // chain B on s2 (or serialized fallback)
    k_cvtw<<<gW, T, 0, sb>>>(W0, W1, W2);
    k_gemm_f32in<<<gGemm, T, SMEM_GEMM, sb>>>(x, w16, hB, NN);
    k_cvt_batch<<<gN, T, 0, sb>>>(bat);
    if (streams_ok) {
        cudaEventRecord(ev1, s2);
        cudaStreamWaitEvent(0, ev1, 0);
    }

    k_gather<<<gGather, T>>>(hB, hA, 1);                        // layer 1 agg
    k_gemm<<<gGemm, T, SMEM_GEMM>>>(hA, w16 + HH * HH, hB, NN);
    k_gather<<<gGather, T>>>(hB, hA, 1);                        // layer 2
    k_gemm<<<gGemm, T, SMEM_GEMM>>>(hA, w16 + 2 * HH * HH, hB, NN);
    k_gather<<<gGather, T>>>(hB, hA, 0);                        // layer 3

    k_pool<<<(NN + 255) / 256, 128>>>(hA);
    k_mlp<<<GG, 128>>>(M0w, M0b, M1w, M1b, out);
}